// round 8
// baseline (speedup 1.0000x reference)
#include <cuda_runtime.h>
#include <math.h>

#define B_  2
#define S_  2048
#define D_  1024
#define H_  16
#define DK_ 64
#define M_  (B_*S_)   // 4096

// ---------------- scratch ----------------
__device__ float g_q[(size_t)B_*H_*S_*DK_];   // [b,h,s,dk]
__device__ float g_k[(size_t)B_*H_*S_*DK_];
__device__ float g_v[(size_t)B_*H_*S_*DK_];
__device__ float g_o[(size_t)M_*D_];          // attention output [b,s,d]
__device__ float g_m[B_*H_*S_];
__device__ float g_l[B_*H_*S_];
__device__ float g_cos[S_*32];
__device__ float g_sin[S_*32];

// ---------------- helpers ----------------
__device__ __forceinline__ unsigned f2tf(float f) {
    unsigned u;
    asm("cvt.rna.tf32.f32 %0, %1;" : "=r"(u) : "f"(f));
    return u;
}
__device__ __forceinline__ void mma_tf32(float* d, const unsigned* a, unsigned b0, unsigned b1) {
    asm volatile("mma.sync.aligned.m16n8k8.row.col.f32.tf32.tf32.f32 "
        "{%0,%1,%2,%3}, {%4,%5,%6,%7}, {%8,%9}, {%0,%1,%2,%3};"
        : "+f"(d[0]), "+f"(d[1]), "+f"(d[2]), "+f"(d[3])
        : "r"(a[0]), "r"(a[1]), "r"(a[2]), "r"(a[3]), "r"(b0), "r"(b1));
}
// swizzle mask for [k][128] tiles; constant per fragment load => conflict-free
__device__ __forceinline__ int xm(int k) {
    return ((k & 3) << 3) ^ (((k >> 2) & 7) << 2);
}

// ---------------- RoPE table ----------------
__global__ void rope_table_kernel() {
    int idx = blockIdx.x * blockDim.x + threadIdx.x;
    if (idx >= S_*32) return;
    int s = idx >> 5, p = idx & 31;
    double ang = (double)s * pow(10000.0, -(double)(2*p) / 64.0);
    g_cos[idx] = (float)cos(ang);
    g_sin[idx] = (float)sin(ang);
}

// ============ tf32 tensor-core GEMM: C[4096,1024] = A @ W^T + bias ============
// 128x128 block, ktile 32, 8 warps (warp: 32m x 64n), double-buffered smem.
template<int HEADOUT>
__device__ __forceinline__ void gemm_tc(
    const float* __restrict__ A, const float* __restrict__ W,
    const float* __restrict__ bias, float* __restrict__ C, bool rope)
{
    extern __shared__ unsigned sm_u[];
    unsigned* As = sm_u;          // 2 x [32][128]
    unsigned* Bs = sm_u + 8192;   // 2 x [32][128]
    const int tid = threadIdx.x;
    const int lane = tid & 31, wid = tid >> 5;
    const int wm0 = (wid & 3) * 32, wn0 = (wid >> 2) * 64;
    const int m0 = blockIdx.y * 128, n0 = blockIdx.x * 128;
    const int c = lane & 3, rq = lane >> 2;

    float acc[2][8][4];
    #pragma unroll
    for (int i = 0; i < 2; i++)
        #pragma unroll
        for (int j = 0; j < 8; j++)
            #pragma unroll
            for (int t = 0; t < 4; t++) acc[i][j][t] = 0.f;

    float4 pa[4], pb[4];
    #pragma unroll
    for (int r = 0; r < 4; r++) {
        int id = tid + r*256, row = id >> 3, kg = id & 7;
        pa[r] = *(const float4*)(A + (size_t)(m0 + row) * D_ + kg*4);
        pb[r] = *(const float4*)(W + (size_t)(n0 + row) * D_ + kg*4);
    }
    // store ktile 0 into buf 0
    #pragma unroll
    for (int r = 0; r < 4; r++) {
        int id = tid + r*256, row = id >> 3, kg = id & 7;
        float av[4] = {pa[r].x, pa[r].y, pa[r].z, pa[r].w};
        float bv[4] = {pb[r].x, pb[r].y, pb[r].z, pb[r].w};
        #pragma unroll
        for (int q = 0; q < 4; q++) {
            int k = kg*4 + q, xs = (q << 3) ^ (kg << 2);
            As[(k << 7) | (row ^ xs)] = f2tf(av[q]);
            Bs[(k << 7) | (row ^ xs)] = f2tf(bv[q]);
        }
    }

    for (int kt = 0; kt < 32; kt++) {
        __syncthreads();
        if (kt < 31) {
            #pragma unroll
            for (int r = 0; r < 4; r++) {
                int id = tid + r*256, row = id >> 3, kg = id & 7;
                pa[r] = *(const float4*)(A + (size_t)(m0 + row) * D_ + (kt+1)*32 + kg*4);
                pb[r] = *(const float4*)(W + (size_t)(n0 + row) * D_ + (kt+1)*32 + kg*4);
            }
        }
        const unsigned* Ab = As + (kt & 1) * 4096;
        const unsigned* Bb = Bs + (kt & 1) * 4096;
        #pragma unroll
        for (int ks = 0; ks < 4; ks++) {
            int x0 = (c << 3) ^ (((ks*2) & 7) << 2);
            int x1 = (c << 3) ^ (((ks*2+1) & 7) << 2);
            int p0 = (ks*8 + c) << 7, p1 = (ks*8 + c + 4) << 7;
            unsigned a[2][4];
            #pragma unroll
            for (int i = 0; i < 2; i++) {
                int r0 = wm0 + i*16 + rq;
                a[i][0] = Ab[p0 | (r0 ^ x0)];
                a[i][1] = Ab[p0 | ((r0+8) ^ x0)];
                a[i][2] = Ab[p1 | (r0 ^ x1)];
                a[i][3] = Ab[p1 | ((r0+8) ^ x1)];
            }
            #pragma unroll
            for (int j = 0; j < 8; j++) {
                int n = wn0 + j*8 + rq;
                unsigned b0 = Bb[p0 | (n ^ x0)];
                unsigned b1 = Bb[p1 | (n ^ x1)];
                mma_tf32(acc[0][j], a[0], b0, b1);
                mma_tf32(acc[1][j], a[1], b0, b1);
            }
        }
        if (kt < 31) {
            unsigned* An = As + ((kt+1) & 1) * 4096;
            unsigned* Bn = Bs + ((kt+1) & 1) * 4096;
            #pragma unroll
            for (int r = 0; r < 4; r++) {
                int id = tid + r*256, row = id >> 3, kg = id & 7;
                float av[4] = {pa[r].x, pa[r].y, pa[r].z, pa[r].w};
                float bv[4] = {pb[r].x, pb[r].y, pb[r].z, pb[r].w};
                #pragma unroll
                for (int q = 0; q < 4; q++) {
                    int k = kg*4 + q, xs = (q << 3) ^ (kg << 2);
                    An[(k << 7) | (row ^ xs)] = f2tf(av[q]);
                    Bn[(k << 7) | (row ^ xs)] = f2tf(bv[q]);
                }
            }
        }
    }

    #pragma unroll
    for (int i = 0; i < 2; i++) {
        #pragma unroll
        for (int j = 0; j < 8; j++) {
            int col = n0 + wn0 + j*8 + c*2;
            float b0v = bias[col], b1v = bias[col+1];
            #pragma unroll
            for (int hf = 0; hf < 2; hf++) {
                int r = m0 + wm0 + i*16 + rq + hf*8;
                float v0 = acc[i][j][hf*2]   + b0v;
                float v1 = acc[i][j][hf*2+1] + b1v;
                if (HEADOUT) {
                    int b = r >> 11, s = r & (S_-1);
                    if (rope) {
                        int p = (col & 63) >> 1;
                        float co = g_cos[(s << 5) + p];
                        float si = g_sin[(s << 5) + p];
                        float e = v0, o = v1;
                        v0 = e*co - o*si;
                        v1 = o*co + e*si;
                    }
                    int h = col >> 6;
                    *(float2*)(C + (((size_t)(b*H_ + h) * S_) + s) * DK_ + (col & 63)) =
                        make_float2(v0, v1);
                } else {
                    *(float2*)(C + (size_t)r * D_ + col) = make_float2(v0, v1);
                }
            }
        }
    }
}

__global__ __launch_bounds__(256) void qkv_gemm(
    const float* __restrict__ Q, const float* __restrict__ K, const float* __restrict__ V,
    const float* __restrict__ Wq, const float* __restrict__ Wk, const float* __restrict__ Wv,
    const float* __restrict__ bq, const float* __restrict__ bk, const float* __restrict__ bv)
{
    int z = blockIdx.z;
    const float* A    = (z==0) ? Q  : (z==1) ? K  : V;
    const float* W    = (z==0) ? Wq : (z==1) ? Wk : Wv;
    const float* bias = (z==0) ? bq : (z==1) ? bk : bv;
    float* C          = (z==0) ? g_q : (z==1) ? g_k : g_v;
    gemm_tc<1>(A, W, bias, C, z < 2);
}

__global__ __launch_bounds__(256) void out_gemm(
    const float* __restrict__ W, const float* __restrict__ bias, float* __restrict__ C)
{
    gemm_tc<0>(g_o, W, bias, C, false);
}

// ---------------- shared tile loaders for attention ----------------
// load 128 x 64 fp32 tile -> tf32 smem [k=64][row=128] swizzled; optional scale
__device__ __forceinline__ void load_kmajor(const float* __restrict__ src,
                                            unsigned* dst, int tid, float scale)
{
    #pragma unroll
    for (int r = 0; r < 8; r++) {
        int id = tid + r*256, row = id >> 4, dg = id & 15;
        float4 q = *(const float4*)(src + (size_t)row * DK_ + dg*4);
        q.x *= scale; q.y *= scale; q.z *= scale; q.w *= scale;
        float qa[4] = {q.x, q.y, q.z, q.w};
        #pragma unroll
        for (int cc = 0; cc < 4; cc++) {
            int k = dg*4 + cc;
            dst[(k << 7) | (row ^ xm(k))] = f2tf(qa[cc]);
        }
    }
}

// S = Q @ K^T for one 128x128 tile; warp wid owns rows wid*16..+15, all 128 cols.
__device__ __forceinline__ void s_mma(const unsigned* Qs, const unsigned* Ks,
                                      float sacc[16][4], int wid, int lane)
{
    const int c = lane & 3, rq = lane >> 2;
    #pragma unroll
    for (int ks = 0; ks < 8; ks++) {
        int x0 = (c << 3) ^ (((ks*2) & 7) << 2);
        int x1 = (c << 3) ^ (((ks*2+1) & 7) << 2);
        int p0 = (ks*8 + c) << 7, p1 = (ks*8 + c + 4) << 7;
        int r0 = wid*16 + rq;
        unsigned a[4];
        a[0] = Qs[p0 | (r0 ^ x0)];
        a[1] = Qs[p0 | ((r0+8) ^ x0)];
        a[2] = Qs[p1 | (r0 ^ x1)];
        a[3] = Qs[p1 | ((r0+8) ^ x1)];
        #pragma unroll
        for (int j = 0; j < 16; j++) {
            int n = j*8 + rq;
            unsigned b0 = Ks[p0 | (n ^ x0)];
            unsigned b1 = Ks[p1 | (n ^ x1)];
            mma_tf32(sacc[j], a, b0, b1);
        }
    }
}

// ================= attention pass 1: flash (m, l, O), no spill =================
__global__ __launch_bounds__(256) void attn_pass1() {
    extern __shared__ unsigned smu[];
    unsigned* Qs = smu;            // [64][128]
    unsigned* Ks = smu + 8192;     // [64][128]
    unsigned* Vs = smu + 16384;    // [128][64]
    unsigned* Ps = smu + 24576;    // [128][128]

    const int tid = threadIdx.x;
    const int lane = tid & 31, wid = tid >> 5;
    const int c = lane & 3, rq = lane >> 2;
    const int qt = 15 - (int)blockIdx.x;
    const int bh = blockIdx.y;
    const float* qb = g_q + (size_t)bh * S_ * DK_;
    const float* kb = g_k + (size_t)bh * S_ * DK_;
    const float* vb = g_v + (size_t)bh * S_ * DK_;

    load_kmajor(qb + (size_t)qt*128*DK_, Qs, tid, 0.125f);

    float oacc[8][4];
    #pragma unroll
    for (int j = 0; j < 8; j++)
        #pragma unroll
        for (int t = 0; t < 4; t++) oacc[j][t] = 0.f;
    float mr0 = -1e30f, mr1 = -1e30f, lr0 = 0.f, lr1 = 0.f;
    __syncthreads();

    for (int kt = 0; kt <= qt; kt++) {
        load_kmajor(kb + (size_t)kt*128*DK_, Ks, tid, 1.0f);
        // V: [row=128][d=64] tf32, swizzled by (row&3)<<3, vectorized store
        #pragma unroll
        for (int r = 0; r < 8; r++) {                    // FIXED: full 128x64 tile
            int id = tid + r*256, row = id >> 4, dg = id & 15;
            float4 v = *(const float4*)(vb + (size_t)(kt*128 + row) * DK_ + dg*4);
            uint4 u = make_uint4(f2tf(v.x), f2tf(v.y), f2tf(v.z), f2tf(v.w));
            *(uint4*)&Vs[(row << 6) | ((dg*4) ^ ((row & 3) << 3))] = u;
        }
        __syncthreads();

        float sacc[16][4];
        #pragma unroll
        for (int j = 0; j < 16; j++)
            #pragma unroll
            for (int t = 0; t < 4; t++) sacc[j][t] = 0.f;
        s_mma(Qs, Ks, sacc, wid, lane);

        // causal mask on diagonal tile
        if (kt == qt) {
            int r0 = wid*16 + rq, r1 = r0 + 8;
            #pragma unroll
            for (int j = 0; j < 16; j++) {
                int col = j*8 + c*2;
                if (col   > r0) sacc[j][0] = -1e30f;
                if (col+1 > r0) sacc[j][1] = -1e30f;
                if (col   > r1) sacc[j][2] = -1e30f;
                if (col+1 > r1) sacc[j][3] = -1e30f;
            }
        }
        // row max (4 lanes per row share via shfl over lane&3)
        float rm0 = -1e30f, rm1 = -1e30f;
        #pragma unroll
        for (int j = 0; j < 16; j++) {
            rm0 = fmaxf(rm0, fmaxf(sacc[j][0], sacc[j][1]));
            rm1 = fmaxf(rm1, fmaxf(sacc[j][2], sacc[j][3]));
        }
        rm0 = fmaxf(rm0, __shfl_xor_sync(0xffffffffu, rm0, 1));
        rm0 = fmaxf(rm0, __shfl_xor_sync(0xffffffffu, rm0, 2));
        rm1 = fmaxf(rm1, __shfl_xor_sync(0xffffffffu, rm1, 1));
        rm1 = fmaxf(rm1, __shfl_xor_sync(0xffffffffu, rm1, 2));
        float mn0 = fmaxf(mr0, rm0), mn1 = fmaxf(mr1, rm1);
        float cr0 = __expf(mr0 - mn0), cr1 = __expf(mr1 - mn1);
        float s20 = 0.f, s21 = 0.f;
        int r0 = wid*16 + rq;
        #pragma unroll
        for (int j = 0; j < 16; j++) {
            float p0 = __expf(sacc[j][0] - mn0);
            float p1 = __expf(sacc[j][1] - mn0);
            float p2 = __expf(sacc[j][2] - mn1);
            float p3 = __expf(sacc[j][3] - mn1);
            s20 += p0 + p1; s21 += p2 + p3;
            int col = j*8 + c*2;
            Ps[((col  ) << 7) | (r0     ^ xm(col  ))] = f2tf(p0);
            Ps[((col+1) << 7) | (r0     ^ xm(col+1))] = f2tf(p1);
            Ps[((col  ) << 7) | ((r0+8) ^ xm(col  ))] = f2tf(p2);
            Ps[((col+1) << 7) | ((r0+8) ^ xm(col+1))] = f2tf(p3);
        }
        s20 += __shfl_xor_sync(0xffffffffu, s20, 1);
        s20 += __shfl_xor_sync(0xffffffffu, s20, 2);
        s21 += __shfl_xor_sync(0xffffffffu, s21, 1);
        s21 += __shfl_xor_sync(0xffffffffu, s21, 2);
        lr0 = lr0*cr0 + s20;  lr1 = lr1*cr1 + s21;
        mr0 = mn0;            mr1 = mn1;
        #pragma unroll
        for (int j = 0; j < 8; j++) {
            oacc[j][0] *= cr0; oacc[j][1] *= cr0;
            oacc[j][2] *= cr1; oacc[j][3] *= cr1;
        }
        __syncwarp();
        // O += P @ V   (P rows are warp-private)
        #pragma unroll
        for (int ks = 0; ks < 16; ks++) {
            int k0 = ks*8 + c, k1 = k0 + 4;
            int x0 = (c << 3) ^ (((ks*2) & 7) << 2);
            int x1 = (c << 3) ^ (((ks*2+1) & 7) << 2);
            unsigned a[4];
            a[0] = Ps[(k0 << 7) | (r0 ^ x0)];
            a[1] = Ps[(k0 << 7) | ((r0+8) ^ x0)];
            a[2] = Ps[(k1 << 7) | (r0 ^ x1)];
            a[3] = Ps[(k1 << 7) | ((r0+8) ^ x1)];
            #pragma unroll
            for (int j = 0; j < 8; j++) {
                int d = j*8 + rq;
                unsigned b0 = Vs[(k0 << 6) | (d ^ (c << 3))];
                unsigned b1 = Vs[(k1 << 6) | (d ^ (c << 3))];
                mma_tf32(oacc[j], a, b0, b1);
            }
        }
        __syncthreads();
    }

    const int b = bh >> 4, h = bh & 15;
    const int r0 = wid*16 + rq;
    float rl0 = 1.0f / lr0, rl1 = 1.0f / lr1;
    int s0 = qt*128 + r0, s1 = s0 + 8;
    #pragma unroll
    for (int j = 0; j < 8; j++) {
        int d = j*8 + c*2;
        *(float2*)(g_o + ((size_t)(b*S_ + s0))*D_ + h*DK_ + d) =
            make_float2(oacc[j][0]*rl0, oacc[j][1]*rl0);
        *(float2*)(g_o + ((size_t)(b*S_ + s1))*D_ + h*DK_ + d) =
            make_float2(oacc[j][2]*rl1, oacc[j][3]*rl1);
    }
    if (c == 0) {
        g_m[(size_t)bh*S_ + s0] = mr0;  g_l[(size_t)bh*S_ + s0] = lr0;
        g_m[(size_t)bh*S_ + s1] = mr1;  g_l[(size_t)bh*S_ + s1] = lr1;
    }
}

// ====== pass 2: recompute S, write attn = exp(s-m)/l; zeros above diagonal ======
__global__ __launch_bounds__(256) void attn_pass2(float* __restrict__ attn) {
    const int tid = threadIdx.x;
    const int kvt = blockIdx.x, qt = blockIdx.y, bh = blockIdx.z;
    float* base = attn + (size_t)bh * S_ * S_;

    if (kvt > qt) {   // pure zero tile
        float4 z = make_float4(0.f, 0.f, 0.f, 0.f);
        #pragma unroll
        for (int r = 0; r < 16; r++) {
            int id = tid + r*256, row = id >> 5, cg = id & 31;
            *(float4*)(base + (size_t)(qt*128 + row) * S_ + kvt*128 + cg*4) = z;
        }
        return;
    }

    extern __shared__ unsigned smu[];
    unsigned* Qs = smu;
    unsigned* Ks = smu + 8192;
    const int lane = tid & 31, wid = tid >> 5;
    const int c = lane & 3, rq = lane >> 2;
    const float* qb = g_q + (size_t)bh * S_ * DK_;
    const float* kb = g_k + (size_t)bh * S_ * DK_;

    load_kmajor(qb + (size_t)qt*128*DK_, Qs, tid, 0.125f);
    load_kmajor(kb + (size_t)kvt*128*DK_, Ks, tid, 1.0f);
    __syncthreads();

    float sacc[16][4];
    #pragma unroll
    for (int j = 0; j < 16; j++)
        #pragma unroll
        for (int t = 0; t < 4; t++) sacc[j][t] = 0.f;
    s_mma(Qs, Ks, sacc, wid, lane);

    const int r0 = wid*16 + rq, r1 = r0 + 8;
    const int rg0 = qt*128 + r0, rg1 = qt*128 + r1;
    float m0v = g_m[(size_t)bh*S_ + rg0], rl0 = 1.0f / g_l[(size_t)bh*S_ + rg0];
    float m1v = g_m[(size_t)bh*S_ + rg1], rl1 = 1.0f / g_l[(size_t)bh*S_ + rg1];
    const bool diag = (kvt == qt);

    #pragma unroll
    for (int j = 0; j < 16; j++) {
        int colg = kvt*128 + j*8 + c*2;
        float p0 = __expf(sacc[j][0] - m0v) * rl0;
        float p1 = __expf(sacc[j][1] - m0v) * rl0;
        float p2 = __expf(sacc[j][2] - m1v) * rl1;
        float p3 = __expf(sacc[j][3] - m1v) * rl1;
        if (diag) {
            if (colg   > rg0) p0 = 0.f;
            if (colg+1 > rg0) p1 = 0.f;
            if (colg   > rg1) p2 = 0.f;
            if (colg+1 > rg1) p3 = 0.f;
        }
        *(float2*)(base + (size_t)rg0 * S_ + colg) = make_float2(p0, p1);
        *(float2*)(base + (size_t)rg1 * S_ + colg) = make_float2(p2, p3);
    }
}

// ---------------- launcher ----------------
extern "C" void kernel_launch(void* const* d_in, const int* in_sizes, int n_in,
                              void* d_out, int out_size) {
    const float* Q  = (const float*)d_in[0];
    const float* K  = (const float*)d_in[1];
    const float* V  = (const float*)d_in[2];
    const float* Wq = (const float*)d_in[3];
    const float* bq = (const float*)d_in[4];
    const float* Wk = (const float*)d_in[5];
    const float* bk = (const float*)d_in[6];
    const float* Wv = (const float*)d_in[7];
    const float* bv = (const float*)d_in[8];
    const float* Wo = (const float*)d_in[9];
    const float* bo = (const float*)d_in[10];

    float* out = (float*)d_out;
    size_t attn_off = (size_t)M_*D_;
    float* attn = ((size_t)out_size >= attn_off + (size_t)B_*H_*S_*S_)
                  ? out + attn_off : nullptr;

    cudaFuncSetAttribute(qkv_gemm,   cudaFuncAttributeMaxDynamicSharedMemorySize, 65536);
    cudaFuncSetAttribute(out_gemm,   cudaFuncAttributeMaxDynamicSharedMemorySize, 65536);
    cudaFuncSetAttribute(attn_pass1, cudaFuncAttributeMaxDynamicSharedMemorySize, 163840);
    cudaFuncSetAttribute(attn_pass2, cudaFuncAttributeMaxDynamicSharedMemorySize, 65536);

    rope_table_kernel<<<256, 256>>>();
    qkv_gemm<<<dim3(8, 32, 3), 256, 65536>>>(Q, K, V, Wq, Wk, Wv, bq, bk, bv);
    attn_pass1<<<dim3(16, 32), 256, 163840>>>();
    if (attn) attn_pass2<<<dim3(16, 16, 32), 256, 65536>>>(attn);
    out_gemm<<<dim3(8, 32), 256, 65536>>>(Wo, bo, out);
}

// round 9
// speedup vs baseline: 1.0001x; 1.0001x over previous
#include <cuda_runtime.h>
#include <math.h>

#define B_  2
#define S_  2048
#define D_  1024
#define H_  16
#define DK_ 64
#define M_  (B_*S_)   // 4096

// ---------------- scratch ----------------
__device__ float g_q[(size_t)B_*H_*S_*DK_];   // [b,h,s,dk]
__device__ float g_k[(size_t)B_*H_*S_*DK_];
__device__ float g_v[(size_t)B_*H_*S_*DK_];
__device__ float g_o[(size_t)M_*D_];          // attention output [b,s,d]
__device__ float g_m[B_*H_*S_];
__device__ float g_l[B_*H_*S_];
__device__ float g_cos[S_*32];
__device__ float g_sin[S_*32];

// ---------------- helpers ----------------
__device__ __forceinline__ unsigned f2tf(float f) {
    unsigned u;
    asm("cvt.rna.tf32.f32 %0, %1;" : "=r"(u) : "f"(f));
    return u;
}
__device__ __forceinline__ void mma_tf32(float* d, const unsigned* a, unsigned b0, unsigned b1) {
    asm volatile("mma.sync.aligned.m16n8k8.row.col.f32.tf32.tf32.f32 "
        "{%0,%1,%2,%3}, {%4,%5,%6,%7}, {%8,%9}, {%0,%1,%2,%3};"
        : "+f"(d[0]), "+f"(d[1]), "+f"(d[2]), "+f"(d[3])
        : "r"(a[0]), "r"(a[1]), "r"(a[2]), "r"(a[3]), "r"(b0), "r"(b1));
}
// swizzle mask for [k][128] tiles; constant per fragment load => conflict-free
__device__ __forceinline__ int xm(int k) {
    return ((k & 3) << 3) ^ (((k >> 2) & 7) << 2);
}

// ---------------- RoPE table ----------------
__global__ void rope_table_kernel() {
    int idx = blockIdx.x * blockDim.x + threadIdx.x;
    if (idx >= S_*32) return;
    int s = idx >> 5, p = idx & 31;
    double ang = (double)s * pow(10000.0, -(double)(2*p) / 64.0);
    g_cos[idx] = (float)cos(ang);
    g_sin[idx] = (float)sin(ang);
}

// ============ tf32 tensor-core GEMM: C[4096,1024] = A @ W^T + bias ============
// 128x128 block, ktile 32, 8 warps (warp: 32m x 64n), double-buffered smem.
template<int HEADOUT>
__device__ __forceinline__ void gemm_tc(
    const float* __restrict__ A, const float* __restrict__ W,
    const float* __restrict__ bias, float* __restrict__ C, bool rope)
{
    extern __shared__ unsigned sm_u[];
    unsigned* As = sm_u;          // 2 x [32][128]
    unsigned* Bs = sm_u + 8192;   // 2 x [32][128]
    const int tid = threadIdx.x;
    const int lane = tid & 31, wid = tid >> 5;
    const int wm0 = (wid & 3) * 32, wn0 = (wid >> 2) * 64;
    const int m0 = blockIdx.y * 128, n0 = blockIdx.x * 128;
    const int c = lane & 3, rq = lane >> 2;

    float acc[2][8][4];
    #pragma unroll
    for (int i = 0; i < 2; i++)
        #pragma unroll
        for (int j = 0; j < 8; j++)
            #pragma unroll
            for (int t = 0; t < 4; t++) acc[i][j][t] = 0.f;

    float4 pa[4], pb[4];
    #pragma unroll
    for (int r = 0; r < 4; r++) {
        int id = tid + r*256, row = id >> 3, kg = id & 7;
        pa[r] = *(const float4*)(A + (size_t)(m0 + row) * D_ + kg*4);
        pb[r] = *(const float4*)(W + (size_t)(n0 + row) * D_ + kg*4);
    }
    // store ktile 0 into buf 0
    #pragma unroll
    for (int r = 0; r < 4; r++) {
        int id = tid + r*256, row = id >> 3, kg = id & 7;
        float av[4] = {pa[r].x, pa[r].y, pa[r].z, pa[r].w};
        float bv[4] = {pb[r].x, pb[r].y, pb[r].z, pb[r].w};
        #pragma unroll
        for (int q = 0; q < 4; q++) {
            int k = kg*4 + q, xs = (q << 3) ^ (kg << 2);
            As[(k << 7) | (row ^ xs)] = f2tf(av[q]);
            Bs[(k << 7) | (row ^ xs)] = f2tf(bv[q]);
        }
    }

    for (int kt = 0; kt < 32; kt++) {
        __syncthreads();
        if (kt < 31) {
            #pragma unroll
            for (int r = 0; r < 4; r++) {
                int id = tid + r*256, row = id >> 3, kg = id & 7;
                pa[r] = *(const float4*)(A + (size_t)(m0 + row) * D_ + (kt+1)*32 + kg*4);
                pb[r] = *(const float4*)(W + (size_t)(n0 + row) * D_ + (kt+1)*32 + kg*4);
            }
        }
        const unsigned* Ab = As + (kt & 1) * 4096;
        const unsigned* Bb = Bs + (kt & 1) * 4096;
        #pragma unroll
        for (int ks = 0; ks < 4; ks++) {
            int x0 = (c << 3) ^ (((ks*2) & 7) << 2);
            int x1 = (c << 3) ^ (((ks*2+1) & 7) << 2);
            int p0 = (ks*8 + c) << 7, p1 = (ks*8 + c + 4) << 7;
            unsigned a[2][4];
            #pragma unroll
            for (int i = 0; i < 2; i++) {
                int r0 = wm0 + i*16 + rq;
                a[i][0] = Ab[p0 | (r0 ^ x0)];
                a[i][1] = Ab[p0 | ((r0+8) ^ x0)];
                a[i][2] = Ab[p1 | (r0 ^ x1)];
                a[i][3] = Ab[p1 | ((r0+8) ^ x1)];
            }
            #pragma unroll
            for (int j = 0; j < 8; j++) {
                int n = wn0 + j*8 + rq;
                unsigned b0 = Bb[p0 | (n ^ x0)];
                unsigned b1 = Bb[p1 | (n ^ x1)];
                mma_tf32(acc[0][j], a[0], b0, b1);
                mma_tf32(acc[1][j], a[1], b0, b1);
            }
        }
        if (kt < 31) {
            unsigned* An = As + ((kt+1) & 1) * 4096;
            unsigned* Bn = Bs + ((kt+1) & 1) * 4096;
            #pragma unroll
            for (int r = 0; r < 4; r++) {
                int id = tid + r*256, row = id >> 3, kg = id & 7;
                float av[4] = {pa[r].x, pa[r].y, pa[r].z, pa[r].w};
                float bv[4] = {pb[r].x, pb[r].y, pb[r].z, pb[r].w};
                #pragma unroll
                for (int q = 0; q < 4; q++) {
                    int k = kg*4 + q, xs = (q << 3) ^ (kg << 2);
                    An[(k << 7) | (row ^ xs)] = f2tf(av[q]);
                    Bn[(k << 7) | (row ^ xs)] = f2tf(bv[q]);
                }
            }
        }
    }

    #pragma unroll
    for (int i = 0; i < 2; i++) {
        #pragma unroll
        for (int j = 0; j < 8; j++) {
            int col = n0 + wn0 + j*8 + c*2;
            float b0v = bias[col], b1v = bias[col+1];
            #pragma unroll
            for (int hf = 0; hf < 2; hf++) {
                int r = m0 + wm0 + i*16 + rq + hf*8;
                float v0 = acc[i][j][hf*2]   + b0v;
                float v1 = acc[i][j][hf*2+1] + b1v;
                if (HEADOUT) {
                    int b = r >> 11, s = r & (S_-1);
                    if (rope) {
                        int p = (col & 63) >> 1;
                        float co = g_cos[(s << 5) + p];
                        float si = g_sin[(s << 5) + p];
                        float e = v0, o = v1;
                        v0 = e*co - o*si;
                        v1 = o*co + e*si;
                    }
                    int h = col >> 6;
                    *(float2*)(C + (((size_t)(b*H_ + h) * S_) + s) * DK_ + (col & 63)) =
                        make_float2(v0, v1);
                } else {
                    *(float2*)(C + (size_t)r * D_ + col) = make_float2(v0, v1);
                }
            }
        }
    }
}

__global__ __launch_bounds__(256) void qkv_gemm(
    const float* __restrict__ Q, const float* __restrict__ K, const float* __restrict__ V,
    const float* __restrict__ Wq, const float* __restrict__ Wk, const float* __restrict__ Wv,
    const float* __restrict__ bq, const float* __restrict__ bk, const float* __restrict__ bv)
{
    int z = blockIdx.z;
    const float* A    = (z==0) ? Q  : (z==1) ? K  : V;
    const float* W    = (z==0) ? Wq : (z==1) ? Wk : Wv;
    const float* bias = (z==0) ? bq : (z==1) ? bk : bv;
    float* C          = (z==0) ? g_q : (z==1) ? g_k : g_v;
    gemm_tc<1>(A, W, bias, C, z < 2);
}

__global__ __launch_bounds__(256) void out_gemm(
    const float* __restrict__ W, const float* __restrict__ bias, float* __restrict__ C)
{
    gemm_tc<0>(g_o, W, bias, C, false);
}

// ---------------- shared tile loaders for attention ----------------
// load 128 x 64 fp32 tile -> tf32 smem [k=64][row=128] swizzled; optional scale
__device__ __forceinline__ void load_kmajor(const float* __restrict__ src,
                                            unsigned* dst, int tid, float scale)
{
    #pragma unroll
    for (int r = 0; r < 8; r++) {
        int id = tid + r*256, row = id >> 4, dg = id & 15;
        float4 q = *(const float4*)(src + (size_t)row * DK_ + dg*4);
        q.x *= scale; q.y *= scale; q.z *= scale; q.w *= scale;
        float qa[4] = {q.x, q.y, q.z, q.w};
        #pragma unroll
        for (int cc = 0; cc < 4; cc++) {
            int k = dg*4 + cc;
            dst[(k << 7) | (row ^ xm(k))] = f2tf(qa[cc]);
        }
    }
}

// S = Q @ K^T for one 128x128 tile; warp wid owns rows wid*16..+15, all 128 cols.
__device__ __forceinline__ void s_mma(const unsigned* Qs, const unsigned* Ks,
                                      float sacc[16][4], int wid, int lane)
{
    const int c = lane & 3, rq = lane >> 2;
    #pragma unroll
    for (int ks = 0; ks < 8; ks++) {
        int x0 = (c << 3) ^ (((ks*2) & 7) << 2);
        int x1 = (c << 3) ^ (((ks*2+1) & 7) << 2);
        int p0 = (ks*8 + c) << 7, p1 = (ks*8 + c + 4) << 7;
        int r0 = wid*16 + rq;
        unsigned a[4];
        a[0] = Qs[p0 | (r0 ^ x0)];
        a[1] = Qs[p0 | ((r0+8) ^ x0)];
        a[2] = Qs[p1 | (r0 ^ x1)];
        a[3] = Qs[p1 | ((r0+8) ^ x1)];
        #pragma unroll
        for (int j = 0; j < 16; j++) {
            int n = j*8 + rq;
            unsigned b0 = Ks[p0 | (n ^ x0)];
            unsigned b1 = Ks[p1 | (n ^ x1)];
            mma_tf32(sacc[j], a, b0, b1);
        }
    }
}

// ================= attention pass 1: flash (m, l, O), no spill =================
__global__ __launch_bounds__(256) void attn_pass1() {
    extern __shared__ unsigned smu[];
    unsigned* Qs = smu;            // [64][128]
    unsigned* Ks = smu + 8192;     // [64][128]
    unsigned* Vs = smu + 16384;    // [128][64]
    unsigned* Ps = smu + 24576;    // [128][128]

    const int tid = threadIdx.x;
    const int lane = tid & 31, wid = tid >> 5;
    const int c = lane & 3, rq = lane >> 2;
    const int qt = 15 - (int)blockIdx.x;
    const int bh = blockIdx.y;
    const float* qb = g_q + (size_t)bh * S_ * DK_;
    const float* kb = g_k + (size_t)bh * S_ * DK_;
    const float* vb = g_v + (size_t)bh * S_ * DK_;

    load_kmajor(qb + (size_t)qt*128*DK_, Qs, tid, 0.125f);

    float oacc[8][4];
    #pragma unroll
    for (int j = 0; j < 8; j++)
        #pragma unroll
        for (int t = 0; t < 4; t++) oacc[j][t] = 0.f;
    float mr0 = -1e30f, mr1 = -1e30f, lr0 = 0.f, lr1 = 0.f;
    __syncthreads();

    for (int kt = 0; kt <= qt; kt++) {
        load_kmajor(kb + (size_t)kt*128*DK_, Ks, tid, 1.0f);
        // V: [row=128][d=64] tf32, swizzled by (row&3)<<3, vectorized store
        #pragma unroll
        for (int r = 0; r < 8; r++) {                    // FIXED: full 128x64 tile
            int id = tid + r*256, row = id >> 4, dg = id & 15;
            float4 v = *(const float4*)(vb + (size_t)(kt*128 + row) * DK_ + dg*4);
            uint4 u = make_uint4(f2tf(v.x), f2tf(v.y), f2tf(v.z), f2tf(v.w));
            *(uint4*)&Vs[(row << 6) | ((dg*4) ^ ((row & 3) << 3))] = u;
        }
        __syncthreads();

        float sacc[16][4];
        #pragma unroll
        for (int j = 0; j < 16; j++)
            #pragma unroll
            for (int t = 0; t < 4; t++) sacc[j][t] = 0.f;
        s_mma(Qs, Ks, sacc, wid, lane);

        // causal mask on diagonal tile
        if (kt == qt) {
            int r0 = wid*16 + rq, r1 = r0 + 8;
            #pragma unroll
            for (int j = 0; j < 16; j++) {
                int col = j*8 + c*2;
                if (col   > r0) sacc[j][0] = -1e30f;
                if (col+1 > r0) sacc[j][1] = -1e30f;
                if (col   > r1) sacc[j][2] = -1e30f;
                if (col+1 > r1) sacc[j][3] = -1e30f;
            }
        }
        // row max (4 lanes per row share via shfl over lane&3)
        float rm0 = -1e30f, rm1 = -1e30f;
        #pragma unroll
        for (int j = 0; j < 16; j++) {
            rm0 = fmaxf(rm0, fmaxf(sacc[j][0], sacc[j][1]));
            rm1 = fmaxf(rm1, fmaxf(sacc[j][2], sacc[j][3]));
        }
        rm0 = fmaxf(rm0, __shfl_xor_sync(0xffffffffu, rm0, 1));
        rm0 = fmaxf(rm0, __shfl_xor_sync(0xffffffffu, rm0, 2));
        rm1 = fmaxf(rm1, __shfl_xor_sync(0xffffffffu, rm1, 1));
        rm1 = fmaxf(rm1, __shfl_xor_sync(0xffffffffu, rm1, 2));
        float mn0 = fmaxf(mr0, rm0), mn1 = fmaxf(mr1, rm1);
        float cr0 = __expf(mr0 - mn0), cr1 = __expf(mr1 - mn1);
        float s20 = 0.f, s21 = 0.f;
        int r0 = wid*16 + rq;
        #pragma unroll
        for (int j = 0; j < 16; j++) {
            float p0 = __expf(sacc[j][0] - mn0);
            float p1 = __expf(sacc[j][1] - mn0);
            float p2 = __expf(sacc[j][2] - mn1);
            float p3 = __expf(sacc[j][3] - mn1);
            s20 += p0 + p1; s21 += p2 + p3;
            int col = j*8 + c*2;
            Ps[((col  ) << 7) | (r0     ^ xm(col  ))] = f2tf(p0);
            Ps[((col+1) << 7) | (r0     ^ xm(col+1))] = f2tf(p1);
            Ps[((col  ) << 7) | ((r0+8) ^ xm(col  ))] = f2tf(p2);
            Ps[((col+1) << 7) | ((r0+8) ^ xm(col+1))] = f2tf(p3);
        }
        s20 += __shfl_xor_sync(0xffffffffu, s20, 1);
        s20 += __shfl_xor_sync(0xffffffffu, s20, 2);
        s21 += __shfl_xor_sync(0xffffffffu, s21, 1);
        s21 += __shfl_xor_sync(0xffffffffu, s21, 2);
        lr0 = lr0*cr0 + s20;  lr1 = lr1*cr1 + s21;
        mr0 = mn0;            mr1 = mn1;
        #pragma unroll
        for (int j = 0; j < 8; j++) {
            oacc[j][0] *= cr0; oacc[j][1] *= cr0;
            oacc[j][2] *= cr1; oacc[j][3] *= cr1;
        }
        __syncwarp();
        // O += P @ V   (P rows are warp-private)
        #pragma unroll
        for (int ks = 0; ks < 16; ks++) {
            int k0 = ks*8 + c, k1 = k0 + 4;
            int x0 = (c << 3) ^ (((ks*2) & 7) << 2);
            int x1 = (c << 3) ^ (((ks*2+1) & 7) << 2);
            unsigned a[4];
            a[0] = Ps[(k0 << 7) | (r0 ^ x0)];
            a[1] = Ps[(k0 << 7) | ((r0+8) ^ x0)];
            a[2] = Ps[(k1 << 7) | (r0 ^ x1)];
            a[3] = Ps[(k1 << 7) | ((r0+8) ^ x1)];
            #pragma unroll
            for (int j = 0; j < 8; j++) {
                int d = j*8 + rq;
                unsigned b0 = Vs[(k0 << 6) | (d ^ (c << 3))];
                unsigned b1 = Vs[(k1 << 6) | (d ^ (c << 3))];
                mma_tf32(oacc[j], a, b0, b1);
            }
        }
        __syncthreads();
    }

    const int b = bh >> 4, h = bh & 15;
    const int r0 = wid*16 + rq;
    float rl0 = 1.0f / lr0, rl1 = 1.0f / lr1;
    int s0 = qt*128 + r0, s1 = s0 + 8;
    #pragma unroll
    for (int j = 0; j < 8; j++) {
        int d = j*8 + c*2;
        *(float2*)(g_o + ((size_t)(b*S_ + s0))*D_ + h*DK_ + d) =
            make_float2(oacc[j][0]*rl0, oacc[j][1]*rl0);
        *(float2*)(g_o + ((size_t)(b*S_ + s1))*D_ + h*DK_ + d) =
            make_float2(oacc[j][2]*rl1, oacc[j][3]*rl1);
    }
    if (c == 0) {
        g_m[(size_t)bh*S_ + s0] = mr0;  g_l[(size_t)bh*S_ + s0] = lr0;
        g_m[(size_t)bh*S_ + s1] = mr1;  g_l[(size_t)bh*S_ + s1] = lr1;
    }
}

// ====== pass 2: recompute S, write attn = exp(s-m)/l; zeros above diagonal ======
__global__ __launch_bounds__(256) void attn_pass2(float* __restrict__ attn) {
    const int tid = threadIdx.x;
    const int kvt = blockIdx.x, qt = blockIdx.y, bh = blockIdx.z;
    float* base = attn + (size_t)bh * S_ * S_;

    if (kvt > qt) {   // pure zero tile
        float4 z = make_float4(0.f, 0.f, 0.f, 0.f);
        #pragma unroll
        for (int r = 0; r < 16; r++) {
            int id = tid + r*256, row = id >> 5, cg = id & 31;
            *(float4*)(base + (size_t)(qt*128 + row) * S_ + kvt*128 + cg*4) = z;
        }
        return;
    }

    extern __shared__ unsigned smu[];
    unsigned* Qs = smu;
    unsigned* Ks = smu + 8192;
    const int lane = tid & 31, wid = tid >> 5;
    const int c = lane & 3, rq = lane >> 2;
    const float* qb = g_q + (size_t)bh * S_ * DK_;
    const float* kb = g_k + (size_t)bh * S_ * DK_;

    load_kmajor(qb + (size_t)qt*128*DK_, Qs, tid, 0.125f);
    load_kmajor(kb + (size_t)kvt*128*DK_, Ks, tid, 1.0f);
    __syncthreads();

    float sacc[16][4];
    #pragma unroll
    for (int j = 0; j < 16; j++)
        #pragma unroll
        for (int t = 0; t < 4; t++) sacc[j][t] = 0.f;
    s_mma(Qs, Ks, sacc, wid, lane);

    const int r0 = wid*16 + rq, r1 = r0 + 8;
    const int rg0 = qt*128 + r0, rg1 = qt*128 + r1;
    float m0v = g_m[(size_t)bh*S_ + rg0], rl0 = 1.0f / g_l[(size_t)bh*S_ + rg0];
    float m1v = g_m[(size_t)bh*S_ + rg1], rl1 = 1.0f / g_l[(size_t)bh*S_ + rg1];
    const bool diag = (kvt == qt);

    #pragma unroll
    for (int j = 0; j < 16; j++) {
        int colg = kvt*128 + j*8 + c*2;
        float p0 = __expf(sacc[j][0] - m0v) * rl0;
        float p1 = __expf(sacc[j][1] - m0v) * rl0;
        float p2 = __expf(sacc[j][2] - m1v) * rl1;
        float p3 = __expf(sacc[j][3] - m1v) * rl1;
        if (diag) {
            if (colg   > rg0) p0 = 0.f;
            if (colg+1 > rg0) p1 = 0.f;
            if (colg   > rg1) p2 = 0.f;
            if (colg+1 > rg1) p3 = 0.f;
        }
        *(float2*)(base + (size_t)rg0 * S_ + colg) = make_float2(p0, p1);
        *(float2*)(base + (size_t)rg1 * S_ + colg) = make_float2(p2, p3);
    }
}

// ---------------- launcher ----------------
extern "C" void kernel_launch(void* const* d_in, const int* in_sizes, int n_in,
                              void* d_out, int out_size) {
    const float* Q  = (const float*)d_in[0];
    const float* K  = (const float*)d_in[1];
    const float* V  = (const float*)d_in[2];
    const float* Wq = (const float*)d_in[3];
    const float* bq = (const float*)d_in[4];
    const float* Wk = (const float*)d_in[5];
    const float* bk = (const float*)d_in[6];
    const float* Wv = (const float*)d_in[7];
    const float* bv = (const float*)d_in[8];
    const float* Wo = (const float*)d_in[9];
    const float* bo = (const float*)d_in[10];

    float* out = (float*)d_out;
    size_t attn_off = (size_t)M_*D_;
    float* attn = ((size_t)out_size >= attn_off + (size_t)B_*H_*S_*S_)
                  ? out + attn_off : nullptr;

    cudaFuncSetAttribute(qkv_gemm,   cudaFuncAttributeMaxDynamicSharedMemorySize, 65536);
    cudaFuncSetAttribute(out_gemm,   cudaFuncAttributeMaxDynamicSharedMemorySize, 65536);
    cudaFuncSetAttribute(attn_pass1, cudaFuncAttributeMaxDynamicSharedMemorySize, 163840);
    cudaFuncSetAttribute(attn_pass2, cudaFuncAttributeMaxDynamicSharedMemorySize, 65536);

    rope_table_kernel<<<256, 256>>>();
    qkv_gemm<<<dim3(8, 32, 3), 256, 65536>>>(Q, K, V, Wq, Wk, Wv, bq, bk, bv);
    attn_pass1<<<dim3(16, 32), 256, 163840>>>();
    if (attn) attn_pass2<<<dim3(16, 16, 32), 256, 65536>>>(attn);
    out_gemm<<<dim3(8, 32), 256, 65536>>>(Wo, bo, out);
}

// round 10
// speedup vs baseline: 1.0025x; 1.0025x over previous
#include <cuda_runtime.h>
#include <math.h>

#define B_  2
#define S_  2048
#define D_  1024
#define H_  16
#define DK_ 64
#define M_  (B_*S_)   // 4096

// ---------------- scratch ----------------
__device__ float g_q[(size_t)B_*H_*S_*DK_];   // [b,h,s,dk]
__device__ float g_k[(size_t)B_*H_*S_*DK_];
__device__ float g_v[(size_t)B_*H_*S_*DK_];
__device__ float g_o[(size_t)M_*D_];          // attention output [b,s,d]
__device__ float g_m[B_*H_*S_];
__device__ float g_l[B_*H_*S_];
__device__ float g_cos[S_*32];
__device__ float g_sin[S_*32];

// ---------------- helpers ----------------
__device__ __forceinline__ unsigned f2tf(float f) {
    unsigned u;
    asm("cvt.rna.tf32.f32 %0, %1;" : "=r"(u) : "f"(f));
    return u;
}
__device__ __forceinline__ void mma_tf32(float* d, const unsigned* a, unsigned b0, unsigned b1) {
    asm volatile("mma.sync.aligned.m16n8k8.row.col.f32.tf32.tf32.f32 "
        "{%0,%1,%2,%3}, {%4,%5,%6,%7}, {%8,%9}, {%0,%1,%2,%3};"
        : "+f"(d[0]), "+f"(d[1]), "+f"(d[2]), "+f"(d[3])
        : "r"(a[0]), "r"(a[1]), "r"(a[2]), "r"(a[3]), "r"(b0), "r"(b1));
}
// swizzle mask for [k][128] tiles; constant per fragment load => conflict-free
__device__ __forceinline__ int xm(int k) {
    return ((k & 3) << 3) ^ (((k >> 2) & 7) << 2);
}

// ---------------- RoPE table ----------------
__global__ void rope_table_kernel() {
    int idx = blockIdx.x * blockDim.x + threadIdx.x;
    if (idx >= S_*32) return;
    int s = idx >> 5, p = idx & 31;
    double ang = (double)s * pow(10000.0, -(double)(2*p) / 64.0);
    g_cos[idx] = (float)cos(ang);
    g_sin[idx] = (float)sin(ang);
}

// ============ tf32 tensor-core GEMM: C[4096,1024] = A @ W^T + bias ============
// 128x128 block, ktile 32, 8 warps (warp: 32m x 64n), double-buffered smem.
template<int HEADOUT>
__device__ __forceinline__ void gemm_tc(
    const float* __restrict__ A, const float* __restrict__ W,
    const float* __restrict__ bias, float* __restrict__ C, bool rope)
{
    extern __shared__ unsigned sm_u[];
    unsigned* As = sm_u;          // 2 x [32][128]
    unsigned* Bs = sm_u + 8192;   // 2 x [32][128]
    const int tid = threadIdx.x;
    const int lane = tid & 31, wid = tid >> 5;
    const int wm0 = (wid & 3) * 32, wn0 = (wid >> 2) * 64;
    const int m0 = blockIdx.y * 128, n0 = blockIdx.x * 128;
    const int c = lane & 3, rq = lane >> 2;

    float acc[2][8][4];
    #pragma unroll
    for (int i = 0; i < 2; i++)
        #pragma unroll
        for (int j = 0; j < 8; j++)
            #pragma unroll
            for (int t = 0; t < 4; t++) acc[i][j][t] = 0.f;

    float4 pa[4], pb[4];
    #pragma unroll
    for (int r = 0; r < 4; r++) {
        int id = tid + r*256, row = id >> 3, kg = id & 7;
        pa[r] = *(const float4*)(A + (size_t)(m0 + row) * D_ + kg*4);
        pb[r] = *(const float4*)(W + (size_t)(n0 + row) * D_ + kg*4);
    }
    // store ktile 0 into buf 0
    #pragma unroll
    for (int r = 0; r < 4; r++) {
        int id = tid + r*256, row = id >> 3, kg = id & 7;
        float av[4] = {pa[r].x, pa[r].y, pa[r].z, pa[r].w};
        float bv[4] = {pb[r].x, pb[r].y, pb[r].z, pb[r].w};
        #pragma unroll
        for (int q = 0; q < 4; q++) {
            int k = kg*4 + q, xs = (q << 3) ^ (kg << 2);
            As[(k << 7) | (row ^ xs)] = f2tf(av[q]);
            Bs[(k << 7) | (row ^ xs)] = f2tf(bv[q]);
        }
    }

    for (int kt = 0; kt < 32; kt++) {
        __syncthreads();
        if (kt < 31) {
            #pragma unroll
            for (int r = 0; r < 4; r++) {
                int id = tid + r*256, row = id >> 3, kg = id & 7;
                pa[r] = *(const float4*)(A + (size_t)(m0 + row) * D_ + (kt+1)*32 + kg*4);
                pb[r] = *(const float4*)(W + (size_t)(n0 + row) * D_ + (kt+1)*32 + kg*4);
            }
        }
        const unsigned* Ab = As + (kt & 1) * 4096;
        const unsigned* Bb = Bs + (kt & 1) * 4096;
        #pragma unroll
        for (int ks = 0; ks < 4; ks++) {
            int x0 = (c << 3) ^ (((ks*2) & 7) << 2);
            int x1 = (c << 3) ^ (((ks*2+1) & 7) << 2);
            int p0 = (ks*8 + c) << 7, p1 = (ks*8 + c + 4) << 7;
            unsigned a[2][4];
            #pragma unroll
            for (int i = 0; i < 2; i++) {
                int r0 = wm0 + i*16 + rq;
                a[i][0] = Ab[p0 | (r0 ^ x0)];
                a[i][1] = Ab[p0 | ((r0+8) ^ x0)];
                a[i][2] = Ab[p1 | (r0 ^ x1)];
                a[i][3] = Ab[p1 | ((r0+8) ^ x1)];
            }
            #pragma unroll
            for (int j = 0; j < 8; j++) {
                int n = wn0 + j*8 + rq;
                unsigned b0 = Bb[p0 | (n ^ x0)];
                unsigned b1 = Bb[p1 | (n ^ x1)];
                mma_tf32(acc[0][j], a[0], b0, b1);
                mma_tf32(acc[1][j], a[1], b0, b1);
            }
        }
        if (kt < 31) {
            unsigned* An = As + ((kt+1) & 1) * 4096;
            unsigned* Bn = Bs + ((kt+1) & 1) * 4096;
            #pragma unroll
            for (int r = 0; r < 4; r++) {
                int id = tid + r*256, row = id >> 3, kg = id & 7;
                float av[4] = {pa[r].x, pa[r].y, pa[r].z, pa[r].w};
                float bv[4] = {pb[r].x, pb[r].y, pb[r].z, pb[r].w};
                #pragma unroll
                for (int q = 0; q < 4; q++) {
                    int k = kg*4 + q, xs = (q << 3) ^ (kg << 2);
                    An[(k << 7) | (row ^ xs)] = f2tf(av[q]);
                    Bn[(k << 7) | (row ^ xs)] = f2tf(bv[q]);
                }
            }
        }
    }

    #pragma unroll
    for (int i = 0; i < 2; i++) {
        #pragma unroll
        for (int j = 0; j < 8; j++) {
            int col = n0 + wn0 + j*8 + c*2;
            float b0v = bias[col], b1v = bias[col+1];
            #pragma unroll
            for (int hf = 0; hf < 2; hf++) {
                int r = m0 + wm0 + i*16 + rq + hf*8;
                float v0 = acc[i][j][hf*2]   + b0v;
                float v1 = acc[i][j][hf*2+1] + b1v;
                if (HEADOUT) {
                    int b = r >> 11, s = r & (S_-1);
                    if (rope) {
                        int p = (col & 63) >> 1;
                        float co = g_cos[(s << 5) + p];
                        float si = g_sin[(s << 5) + p];
                        float e = v0, o = v1;
                        v0 = e*co - o*si;
                        v1 = o*co + e*si;
                    }
                    int h = col >> 6;
                    *(float2*)(C + (((size_t)(b*H_ + h) * S_) + s) * DK_ + (col & 63)) =
                        make_float2(v0, v1);
                } else {
                    *(float2*)(C + (size_t)r * D_ + col) = make_float2(v0, v1);
                }
            }
        }
    }
}

__global__ __launch_bounds__(256) void qkv_gemm(
    const float* __restrict__ Q, const float* __restrict__ K, const float* __restrict__ V,
    const float* __restrict__ Wq, const float* __restrict__ Wk, const float* __restrict__ Wv,
    const float* __restrict__ bq, const float* __restrict__ bk, const float* __restrict__ bv)
{
    int z = blockIdx.z;
    const float* A    = (z==0) ? Q  : (z==1) ? K  : V;
    const float* W    = (z==0) ? Wq : (z==1) ? Wk : Wv;
    const float* bias = (z==0) ? bq : (z==1) ? bk : bv;
    float* C          = (z==0) ? g_q : (z==1) ? g_k : g_v;
    gemm_tc<1>(A, W, bias, C, z < 2);
}

__global__ __launch_bounds__(256) void out_gemm(
    const float* __restrict__ W, const float* __restrict__ bias, float* __restrict__ C)
{
    gemm_tc<0>(g_o, W, bias, C, false);
}

// ---------------- shared tile loaders for attention ----------------
// load 128 x 64 fp32 tile -> tf32 smem [k=64][row=128] swizzled; optional scale
__device__ __forceinline__ void load_kmajor(const float* __restrict__ src,
                                            unsigned* dst, int tid, float scale)
{
    #pragma unroll
    for (int r = 0; r < 8; r++) {
        int id = tid + r*256, row = id >> 4, dg = id & 15;
        float4 q = *(const float4*)(src + (size_t)row * DK_ + dg*4);
        q.x *= scale; q.y *= scale; q.z *= scale; q.w *= scale;
        float qa[4] = {q.x, q.y, q.z, q.w};
        #pragma unroll
        for (int cc = 0; cc < 4; cc++) {
            int k = dg*4 + cc;
            dst[(k << 7) | (row ^ xm(k))] = f2tf(qa[cc]);
        }
    }
}

// S = Q @ K^T for one 128x128 tile; warp wid owns rows wid*16..+15, all 128 cols.
__device__ __forceinline__ void s_mma(const unsigned* Qs, const unsigned* Ks,
                                      float sacc[16][4], int wid, int lane)
{
    const int c = lane & 3, rq = lane >> 2;
    #pragma unroll
    for (int ks = 0; ks < 8; ks++) {
        int x0 = (c << 3) ^ (((ks*2) & 7) << 2);
        int x1 = (c << 3) ^ (((ks*2+1) & 7) << 2);
        int p0 = (ks*8 + c) << 7, p1 = (ks*8 + c + 4) << 7;
        int r0 = wid*16 + rq;
        unsigned a[4];
        a[0] = Qs[p0 | (r0 ^ x0)];
        a[1] = Qs[p0 | ((r0+8) ^ x0)];
        a[2] = Qs[p1 | (r0 ^ x1)];
        a[3] = Qs[p1 | ((r0+8) ^ x1)];
        #pragma unroll
        for (int j = 0; j < 16; j++) {
            int n = j*8 + rq;
            unsigned b0 = Ks[p0 | (n ^ x0)];
            unsigned b1 = Ks[p1 | (n ^ x1)];
            mma_tf32(sacc[j], a, b0, b1);
        }
    }
}

// ================= attention pass 1: flash (m, l, O), no spill =================
__global__ __launch_bounds__(256) void attn_pass1() {
    extern __shared__ unsigned smu[];
    unsigned* Qs = smu;            // [64][128]
    unsigned* Ks = smu + 8192;     // [64][128]
    unsigned* Vs = smu + 16384;    // [128][64]
    unsigned* Ps = smu + 24576;    // [128][128]

    const int tid = threadIdx.x;
    const int lane = tid & 31, wid = tid >> 5;
    const int c = lane & 3, rq = lane >> 2;
    const int qt = 15 - (int)blockIdx.x;
    const int bh = blockIdx.y;
    const float* qb = g_q + (size_t)bh * S_ * DK_;
    const float* kb = g_k + (size_t)bh * S_ * DK_;
    const float* vb = g_v + (size_t)bh * S_ * DK_;

    load_kmajor(qb + (size_t)qt*128*DK_, Qs, tid, 0.125f);

    float oacc[8][4];
    #pragma unroll
    for (int j = 0; j < 8; j++)
        #pragma unroll
        for (int t = 0; t < 4; t++) oacc[j][t] = 0.f;
    float mr0 = -1e30f, mr1 = -1e30f, lr0 = 0.f, lr1 = 0.f;
    __syncthreads();

    for (int kt = 0; kt <= qt; kt++) {
        load_kmajor(kb + (size_t)kt*128*DK_, Ks, tid, 1.0f);
        // V: [row=128][d=64] tf32, swizzled by (row&3)<<3, vectorized store
        #pragma unroll
        for (int r = 0; r < 8; r++) {                    // FIXED: full 128x64 tile
            int id = tid + r*256, row = id >> 4, dg = id & 15;
            float4 v = *(const float4*)(vb + (size_t)(kt*128 + row) * DK_ + dg*4);
            uint4 u = make_uint4(f2tf(v.x), f2tf(v.y), f2tf(v.z), f2tf(v.w));
            *(uint4*)&Vs[(row << 6) | ((dg*4) ^ ((row & 3) << 3))] = u;
        }
        __syncthreads();

        float sacc[16][4];
        #pragma unroll
        for (int j = 0; j < 16; j++)
            #pragma unroll
            for (int t = 0; t < 4; t++) sacc[j][t] = 0.f;
        s_mma(Qs, Ks, sacc, wid, lane);

        // causal mask on diagonal tile
        if (kt == qt) {
            int r0 = wid*16 + rq, r1 = r0 + 8;
            #pragma unroll
            for (int j = 0; j < 16; j++) {
                int col = j*8 + c*2;
                if (col   > r0) sacc[j][0] = -1e30f;
                if (col+1 > r0) sacc[j][1] = -1e30f;
                if (col   > r1) sacc[j][2] = -1e30f;
                if (col+1 > r1) sacc[j][3] = -1e30f;
            }
        }
        // row max (4 lanes per row share via shfl over lane&3)
        float rm0 = -1e30f, rm1 = -1e30f;
        #pragma unroll
        for (int j = 0; j < 16; j++) {
            rm0 = fmaxf(rm0, fmaxf(sacc[j][0], sacc[j][1]));
            rm1 = fmaxf(rm1, fmaxf(sacc[j][2], sacc[j][3]));
        }
        rm0 = fmaxf(rm0, __shfl_xor_sync(0xffffffffu, rm0, 1));
        rm0 = fmaxf(rm0, __shfl_xor_sync(0xffffffffu, rm0, 2));
        rm1 = fmaxf(rm1, __shfl_xor_sync(0xffffffffu, rm1, 1));
        rm1 = fmaxf(rm1, __shfl_xor_sync(0xffffffffu, rm1, 2));
        float mn0 = fmaxf(mr0, rm0), mn1 = fmaxf(mr1, rm1);
        float cr0 = __expf(mr0 - mn0), cr1 = __expf(mr1 - mn1);
        float s20 = 0.f, s21 = 0.f;
        int r0 = wid*16 + rq;
        #pragma unroll
        for (int j = 0; j < 16; j++) {
            float p0 = __expf(sacc[j][0] - mn0);
            float p1 = __expf(sacc[j][1] - mn0);
            float p2 = __expf(sacc[j][2] - mn1);
            float p3 = __expf(sacc[j][3] - mn1);
            s20 += p0 + p1; s21 += p2 + p3;
            int col = j*8 + c*2;
            Ps[((col  ) << 7) | (r0     ^ xm(col  ))] = f2tf(p0);
            Ps[((col+1) << 7) | (r0     ^ xm(col+1))] = f2tf(p1);
            Ps[((col  ) << 7) | ((r0+8) ^ xm(col  ))] = f2tf(p2);
            Ps[((col+1) << 7) | ((r0+8) ^ xm(col+1))] = f2tf(p3);
        }
        s20 += __shfl_xor_sync(0xffffffffu, s20, 1);
        s20 += __shfl_xor_sync(0xffffffffu, s20, 2);
        s21 += __shfl_xor_sync(0xffffffffu, s21, 1);
        s21 += __shfl_xor_sync(0xffffffffu, s21, 2);
        lr0 = lr0*cr0 + s20;  lr1 = lr1*cr1 + s21;
        mr0 = mn0;            mr1 = mn1;
        #pragma unroll
        for (int j = 0; j < 8; j++) {
            oacc[j][0] *= cr0; oacc[j][1] *= cr0;
            oacc[j][2] *= cr1; oacc[j][3] *= cr1;
        }
        __syncwarp();
        // O += P @ V   (P rows are warp-private)
        #pragma unroll
        for (int ks = 0; ks < 16; ks++) {
            int k0 = ks*8 + c, k1 = k0 + 4;
            int x0 = (c << 3) ^ (((ks*2) & 7) << 2);
            int x1 = (c << 3) ^ (((ks*2+1) & 7) << 2);
            unsigned a[4];
            a[0] = Ps[(k0 << 7) | (r0 ^ x0)];
            a[1] = Ps[(k0 << 7) | ((r0+8) ^ x0)];
            a[2] = Ps[(k1 << 7) | (r0 ^ x1)];
            a[3] = Ps[(k1 << 7) | ((r0+8) ^ x1)];
            #pragma unroll
            for (int j = 0; j < 8; j++) {
                int d = j*8 + rq;
                unsigned b0 = Vs[(k0 << 6) | (d ^ (c << 3))];
                unsigned b1 = Vs[(k1 << 6) | (d ^ (c << 3))];
                mma_tf32(oacc[j], a, b0, b1);
            }
        }
        __syncthreads();
    }

    const int b = bh >> 4, h = bh & 15;
    const int r0 = wid*16 + rq;
    float rl0 = 1.0f / lr0, rl1 = 1.0f / lr1;
    int s0 = qt*128 + r0, s1 = s0 + 8;
    #pragma unroll
    for (int j = 0; j < 8; j++) {
        int d = j*8 + c*2;
        *(float2*)(g_o + ((size_t)(b*S_ + s0))*D_ + h*DK_ + d) =
            make_float2(oacc[j][0]*rl0, oacc[j][1]*rl0);
        *(float2*)(g_o + ((size_t)(b*S_ + s1))*D_ + h*DK_ + d) =
            make_float2(oacc[j][2]*rl1, oacc[j][3]*rl1);
    }
    if (c == 0) {
        g_m[(size_t)bh*S_ + s0] = mr0;  g_l[(size_t)bh*S_ + s0] = lr0;
        g_m[(size_t)bh*S_ + s1] = mr1;  g_l[(size_t)bh*S_ + s1] = lr1;
    }
}

// ====== pass 2: recompute S, write attn = exp(s-m)/l; zeros above diagonal ======
__global__ __launch_bounds__(256) void attn_pass2(float* __restrict__ attn) {
    const int tid = threadIdx.x;
    const int kvt = blockIdx.x, qt = blockIdx.y, bh = blockIdx.z;
    float* base = attn + (size_t)bh * S_ * S_;

    if (kvt > qt) {   // pure zero tile
        float4 z = make_float4(0.f, 0.f, 0.f, 0.f);
        #pragma unroll
        for (int r = 0; r < 16; r++) {
            int id = tid + r*256, row = id >> 5, cg = id & 31;
            *(float4*)(base + (size_t)(qt*128 + row) * S_ + kvt*128 + cg*4) = z;
        }
        return;
    }

    extern __shared__ unsigned smu[];
    unsigned* Qs = smu;
    unsigned* Ks = smu + 8192;
    const int lane = tid & 31, wid = tid >> 5;
    const int c = lane & 3, rq = lane >> 2;
    const float* qb = g_q + (size_t)bh * S_ * DK_;
    const float* kb = g_k + (size_t)bh * S_ * DK_;

    load_kmajor(qb + (size_t)qt*128*DK_, Qs, tid, 0.125f);
    load_kmajor(kb + (size_t)kvt*128*DK_, Ks, tid, 1.0f);
    __syncthreads();

    float sacc[16][4];
    #pragma unroll
    for (int j = 0; j < 16; j++)
        #pragma unroll
        for (int t = 0; t < 4; t++) sacc[j][t] = 0.f;
    s_mma(Qs, Ks, sacc, wid, lane);

    const int r0 = wid*16 + rq, r1 = r0 + 8;
    const int rg0 = qt*128 + r0, rg1 = qt*128 + r1;
    float m0v = g_m[(size_t)bh*S_ + rg0], rl0 = 1.0f / g_l[(size_t)bh*S_ + rg0];
    float m1v = g_m[(size_t)bh*S_ + rg1], rl1 = 1.0f / g_l[(size_t)bh*S_ + rg1];
    const bool diag = (kvt == qt);

    #pragma unroll
    for (int j = 0; j < 16; j++) {
        int colg = kvt*128 + j*8 + c*2;
        float p0 = __expf(sacc[j][0] - m0v) * rl0;
        float p1 = __expf(sacc[j][1] - m0v) * rl0;
        float p2 = __expf(sacc[j][2] - m1v) * rl1;
        float p3 = __expf(sacc[j][3] - m1v) * rl1;
        if (diag) {
            if (colg   > rg0) p0 = 0.f;
            if (colg+1 > rg0) p1 = 0.f;
            if (colg   > rg1) p2 = 0.f;
            if (colg+1 > rg1) p3 = 0.f;
        }
        *(float2*)(base + (size_t)rg0 * S_ + colg) = make_float2(p0, p1);
        *(float2*)(base + (size_t)rg1 * S_ + colg) = make_float2(p2, p3);
    }
}

// ---------------- launcher ----------------
extern "C" void kernel_launch(void* const* d_in, const int* in_sizes, int n_in,
                              void* d_out, int out_size) {
    const float* Q  = (const float*)d_in[0];
    const float* K  = (const float*)d_in[1];
    const float* V  = (const float*)d_in[2];
    const float* Wq = (const float*)d_in[3];
    const float* bq = (const float*)d_in[4];
    const float* Wk = (const float*)d_in[5];
    const float* bk = (const float*)d_in[6];
    const float* Wv = (const float*)d_in[7];
    const float* bv = (const float*)d_in[8];
    const float* Wo = (const float*)d_in[9];
    const float* bo = (const float*)d_in[10];

    float* out = (float*)d_out;
    size_t attn_off = (size_t)M_*D_;
    float* attn = ((size_t)out_size >= attn_off + (size_t)B_*H_*S_*S_)
                  ? out + attn_off : nullptr;

    cudaFuncSetAttribute(qkv_gemm,   cudaFuncAttributeMaxDynamicSharedMemorySize, 65536);
    cudaFuncSetAttribute(out_gemm,   cudaFuncAttributeMaxDynamicSharedMemorySize, 65536);
    cudaFuncSetAttribute(attn_pass1, cudaFuncAttributeMaxDynamicSharedMemorySize, 163840);
    cudaFuncSetAttribute(attn_pass2, cudaFuncAttributeMaxDynamicSharedMemorySize, 65536);

    rope_table_kernel<<<256, 256>>>();
    qkv_gemm<<<dim3(8, 32, 3), 256, 65536>>>(Q, K, V, Wq, Wk, Wv, bq, bk, bv);
    attn_pass1<<<dim3(16, 32), 256, 163840>>>();
    if (attn) attn_pass2<<<dim3(16, 16, 32), 256, 65536>>>(attn);
    out_gemm<<<dim3(8, 32), 256, 65536>>>(Wo, bo, out);
}

// round 11
// speedup vs baseline: 1.0029x; 1.0004x over previous
#include <cuda_runtime.h>
#include <math.h>

#define B_  2
#define S_  2048
#define D_  1024
#define H_  16
#define DK_ 64
#define M_  (B_*S_)   // 4096

// ---------------- scratch ----------------
__device__ float g_q[(size_t)B_*H_*S_*DK_];   // [b,h,s,dk]
__device__ float g_k[(size_t)B_*H_*S_*DK_];
__device__ float g_v[(size_t)B_*H_*S_*DK_];
__device__ float g_o[(size_t)M_*D_];          // attention output [b,s,d]
__device__ float g_m[B_*H_*S_];
__device__ float g_l[B_*H_*S_];
__device__ float g_cos[S_*32];
__device__ float g_sin[S_*32];

// ---------------- helpers ----------------
__device__ __forceinline__ unsigned f2tf(float f) {
    unsigned u;
    asm("cvt.rna.tf32.f32 %0, %1;" : "=r"(u) : "f"(f));
    return u;
}
__device__ __forceinline__ void mma_tf32(float* d, const unsigned* a, unsigned b0, unsigned b1) {
    asm volatile("mma.sync.aligned.m16n8k8.row.col.f32.tf32.tf32.f32 "
        "{%0,%1,%2,%3}, {%4,%5,%6,%7}, {%8,%9}, {%0,%1,%2,%3};"
        : "+f"(d[0]), "+f"(d[1]), "+f"(d[2]), "+f"(d[3])
        : "r"(a[0]), "r"(a[1]), "r"(a[2]), "r"(a[3]), "r"(b0), "r"(b1));
}
// swizzle mask for [k][128] tiles; constant per fragment load => conflict-free
__device__ __forceinline__ int xm(int k) {
    return ((k & 3) << 3) ^ (((k >> 2) & 7) << 2);
}

// ---------------- RoPE table ----------------
__global__ void rope_table_kernel() {
    int idx = blockIdx.x * blockDim.x + threadIdx.x;
    if (idx >= S_*32) return;
    int s = idx >> 5, p = idx & 31;
    double ang = (double)s * pow(10000.0, -(double)(2*p) / 64.0);
    g_cos[idx] = (float)cos(ang);
    g_sin[idx] = (float)sin(ang);
}

// ============ tf32 tensor-core GEMM: C[4096,1024] = A @ W^T + bias ============
// 128x128 block, ktile 32, 8 warps (warp: 32m x 64n), double-buffered smem.
template<int HEADOUT>
__device__ __forceinline__ void gemm_tc(
    const float* __restrict__ A, const float* __restrict__ W,
    const float* __restrict__ bias, float* __restrict__ C, bool rope)
{
    extern __shared__ unsigned sm_u[];
    unsigned* As = sm_u;          // 2 x [32][128]
    unsigned* Bs = sm_u + 8192;   // 2 x [32][128]
    const int tid = threadIdx.x;
    const int lane = tid & 31, wid = tid >> 5;
    const int wm0 = (wid & 3) * 32, wn0 = (wid >> 2) * 64;
    const int m0 = blockIdx.y * 128, n0 = blockIdx.x * 128;
    const int c = lane & 3, rq = lane >> 2;

    float acc[2][8][4];
    #pragma unroll
    for (int i = 0; i < 2; i++)
        #pragma unroll
        for (int j = 0; j < 8; j++)
            #pragma unroll
            for (int t = 0; t < 4; t++) acc[i][j][t] = 0.f;

    float4 pa[4], pb[4];
    #pragma unroll
    for (int r = 0; r < 4; r++) {
        int id = tid + r*256, row = id >> 3, kg = id & 7;
        pa[r] = *(const float4*)(A + (size_t)(m0 + row) * D_ + kg*4);
        pb[r] = *(const float4*)(W + (size_t)(n0 + row) * D_ + kg*4);
    }
    // store ktile 0 into buf 0
    #pragma unroll
    for (int r = 0; r < 4; r++) {
        int id = tid + r*256, row = id >> 3, kg = id & 7;
        float av[4] = {pa[r].x, pa[r].y, pa[r].z, pa[r].w};
        float bv[4] = {pb[r].x, pb[r].y, pb[r].z, pb[r].w};
        #pragma unroll
        for (int q = 0; q < 4; q++) {
            int k = kg*4 + q, xs = (q << 3) ^ (kg << 2);
            As[(k << 7) | (row ^ xs)] = f2tf(av[q]);
            Bs[(k << 7) | (row ^ xs)] = f2tf(bv[q]);
        }
    }

    for (int kt = 0; kt < 32; kt++) {
        __syncthreads();
        if (kt < 31) {
            #pragma unroll
            for (int r = 0; r < 4; r++) {
                int id = tid + r*256, row = id >> 3, kg = id & 7;
                pa[r] = *(const float4*)(A + (size_t)(m0 + row) * D_ + (kt+1)*32 + kg*4);
                pb[r] = *(const float4*)(W + (size_t)(n0 + row) * D_ + (kt+1)*32 + kg*4);
            }
        }
        const unsigned* Ab = As + (kt & 1) * 4096;
        const unsigned* Bb = Bs + (kt & 1) * 4096;
        #pragma unroll
        for (int ks = 0; ks < 4; ks++) {
            int x0 = (c << 3) ^ (((ks*2) & 7) << 2);
            int x1 = (c << 3) ^ (((ks*2+1) & 7) << 2);
            int p0 = (ks*8 + c) << 7, p1 = (ks*8 + c + 4) << 7;
            unsigned a[2][4];
            #pragma unroll
            for (int i = 0; i < 2; i++) {
                int r0 = wm0 + i*16 + rq;
                a[i][0] = Ab[p0 | (r0 ^ x0)];
                a[i][1] = Ab[p0 | ((r0+8) ^ x0)];
                a[i][2] = Ab[p1 | (r0 ^ x1)];
                a[i][3] = Ab[p1 | ((r0+8) ^ x1)];
            }
            #pragma unroll
            for (int j = 0; j < 8; j++) {
                int n = wn0 + j*8 + rq;
                unsigned b0 = Bb[p0 | (n ^ x0)];
                unsigned b1 = Bb[p1 | (n ^ x1)];
                mma_tf32(acc[0][j], a[0], b0, b1);
                mma_tf32(acc[1][j], a[1], b0, b1);
            }
        }
        if (kt < 31) {
            unsigned* An = As + ((kt+1) & 1) * 4096;
            unsigned* Bn = Bs + ((kt+1) & 1) * 4096;
            #pragma unroll
            for (int r = 0; r < 4; r++) {
                int id = tid + r*256, row = id >> 3, kg = id & 7;
                float av[4] = {pa[r].x, pa[r].y, pa[r].z, pa[r].w};
                float bv[4] = {pb[r].x, pb[r].y, pb[r].z, pb[r].w};
                #pragma unroll
                for (int q = 0; q < 4; q++) {
                    int k = kg*4 + q, xs = (q << 3) ^ (kg << 2);
                    An[(k << 7) | (row ^ xs)] = f2tf(av[q]);
                    Bn[(k << 7) | (row ^ xs)] = f2tf(bv[q]);
                }
            }
        }
    }

    #pragma unroll
    for (int i = 0; i < 2; i++) {
        #pragma unroll
        for (int j = 0; j < 8; j++) {
            int col = n0 + wn0 + j*8 + c*2;
            float b0v = bias[col], b1v = bias[col+1];
            #pragma unroll
            for (int hf = 0; hf < 2; hf++) {
                int r = m0 + wm0 + i*16 + rq + hf*8;
                float v0 = acc[i][j][hf*2]   + b0v;
                float v1 = acc[i][j][hf*2+1] + b1v;
                if (HEADOUT) {
                    int b = r >> 11, s = r & (S_-1);
                    if (rope) {
                        int p = (col & 63) >> 1;
                        float co = g_cos[(s << 5) + p];
                        float si = g_sin[(s << 5) + p];
                        float e = v0, o = v1;
                        v0 = e*co - o*si;
                        v1 = o*co + e*si;
                    }
                    int h = col >> 6;
                    *(float2*)(C + (((size_t)(b*H_ + h) * S_) + s) * DK_ + (col & 63)) =
                        make_float2(v0, v1);
                } else {
                    *(float2*)(C + (size_t)r * D_ + col) = make_float2(v0, v1);
                }
            }
        }
    }
}

__global__ __launch_bounds__(256) void qkv_gemm(
    const float* __restrict__ Q, const float* __restrict__ K, const float* __restrict__ V,
    const float* __restrict__ Wq, const float* __restrict__ Wk, const float* __restrict__ Wv,
    const float* __restrict__ bq, const float* __restrict__ bk, const float* __restrict__ bv)
{
    int z = blockIdx.z;
    const float* A    = (z==0) ? Q  : (z==1) ? K  : V;
    const float* W    = (z==0) ? Wq : (z==1) ? Wk : Wv;
    const float* bias = (z==0) ? bq : (z==1) ? bk : bv;
    float* C          = (z==0) ? g_q : (z==1) ? g_k : g_v;
    gemm_tc<1>(A, W, bias, C, z < 2);
}

__global__ __launch_bounds__(256) void out_gemm(
    const float* __restrict__ W, const float* __restrict__ bias, float* __restrict__ C)
{
    gemm_tc<0>(g_o, W, bias, C, false);
}

// ---------------- shared tile loaders for attention ----------------
// load 128 x 64 fp32 tile -> tf32 smem [k=64][row=128] swizzled; optional scale
__device__ __forceinline__ void load_kmajor(const float* __restrict__ src,
                                            unsigned* dst, int tid, float scale)
{
    #pragma unroll
    for (int r = 0; r < 8; r++) {
        int id = tid + r*256, row = id >> 4, dg = id & 15;
        float4 q = *(const float4*)(src + (size_t)row * DK_ + dg*4);
        q.x *= scale; q.y *= scale; q.z *= scale; q.w *= scale;
        float qa[4] = {q.x, q.y, q.z, q.w};
        #pragma unroll
        for (int cc = 0; cc < 4; cc++) {
            int k = dg*4 + cc;
            dst[(k << 7) | (row ^ xm(k))] = f2tf(qa[cc]);
        }
    }
}

// S = Q @ K^T for one 128x128 tile; warp wid owns rows wid*16..+15, all 128 cols.
__device__ __forceinline__ void s_mma(const unsigned* Qs, const unsigned* Ks,
                                      float sacc[16][4], int wid, int lane)
{
    const int c = lane & 3, rq = lane >> 2;
    #pragma unroll
    for (int ks = 0; ks < 8; ks++) {
        int x0 = (c << 3) ^ (((ks*2) & 7) << 2);
        int x1 = (c << 3) ^ (((ks*2+1) & 7) << 2);
        int p0 = (ks*8 + c) << 7, p1 = (ks*8 + c + 4) << 7;
        int r0 = wid*16 + rq;
        unsigned a[4];
        a[0] = Qs[p0 | (r0 ^ x0)];
        a[1] = Qs[p0 | ((r0+8) ^ x0)];
        a[2] = Qs[p1 | (r0 ^ x1)];
        a[3] = Qs[p1 | ((r0+8) ^ x1)];
        #pragma unroll
        for (int j = 0; j < 16; j++) {
            int n = j*8 + rq;
            unsigned b0 = Ks[p0 | (n ^ x0)];
            unsigned b1 = Ks[p1 | (n ^ x1)];
            mma_tf32(sacc[j], a, b0, b1);
        }
    }
}

// ================= attention pass 1: flash (m, l, O), no spill =================
__global__ __launch_bounds__(256) void attn_pass1() {
    extern __shared__ unsigned smu[];
    unsigned* Qs = smu;            // [64][128]
    unsigned* Ks = smu + 8192;     // [64][128]
    unsigned* Vs = smu + 16384;    // [128][64]
    unsigned* Ps = smu + 24576;    // [128][128]

    const int tid = threadIdx.x;
    const int lane = tid & 31, wid = tid >> 5;
    const int c = lane & 3, rq = lane >> 2;
    const int qt = 15 - (int)blockIdx.x;
    const int bh = blockIdx.y;
    const float* qb = g_q + (size_t)bh * S_ * DK_;
    const float* kb = g_k + (size_t)bh * S_ * DK_;
    const float* vb = g_v + (size_t)bh * S_ * DK_;

    load_kmajor(qb + (size_t)qt*128*DK_, Qs, tid, 0.125f);

    float oacc[8][4];
    #pragma unroll
    for (int j = 0; j < 8; j++)
        #pragma unroll
        for (int t = 0; t < 4; t++) oacc[j][t] = 0.f;
    float mr0 = -1e30f, mr1 = -1e30f, lr0 = 0.f, lr1 = 0.f;
    __syncthreads();

    for (int kt = 0; kt <= qt; kt++) {
        load_kmajor(kb + (size_t)kt*128*DK_, Ks, tid, 1.0f);
        // V: [row=128][d=64] tf32, swizzled by (row&3)<<3, vectorized store
        #pragma unroll
        for (int r = 0; r < 8; r++) {                    // FIXED: full 128x64 tile
            int id = tid + r*256, row = id >> 4, dg = id & 15;
            float4 v = *(const float4*)(vb + (size_t)(kt*128 + row) * DK_ + dg*4);
            uint4 u = make_uint4(f2tf(v.x), f2tf(v.y), f2tf(v.z), f2tf(v.w));
            *(uint4*)&Vs[(row << 6) | ((dg*4) ^ ((row & 3) << 3))] = u;
        }
        __syncthreads();

        float sacc[16][4];
        #pragma unroll
        for (int j = 0; j < 16; j++)
            #pragma unroll
            for (int t = 0; t < 4; t++) sacc[j][t] = 0.f;
        s_mma(Qs, Ks, sacc, wid, lane);

        // causal mask on diagonal tile
        if (kt == qt) {
            int r0 = wid*16 + rq, r1 = r0 + 8;
            #pragma unroll
            for (int j = 0; j < 16; j++) {
                int col = j*8 + c*2;
                if (col   > r0) sacc[j][0] = -1e30f;
                if (col+1 > r0) sacc[j][1] = -1e30f;
                if (col   > r1) sacc[j][2] = -1e30f;
                if (col+1 > r1) sacc[j][3] = -1e30f;
            }
        }
        // row max (4 lanes per row share via shfl over lane&3)
        float rm0 = -1e30f, rm1 = -1e30f;
        #pragma unroll
        for (int j = 0; j < 16; j++) {
            rm0 = fmaxf(rm0, fmaxf(sacc[j][0], sacc[j][1]));
            rm1 = fmaxf(rm1, fmaxf(sacc[j][2], sacc[j][3]));
        }
        rm0 = fmaxf(rm0, __shfl_xor_sync(0xffffffffu, rm0, 1));
        rm0 = fmaxf(rm0, __shfl_xor_sync(0xffffffffu, rm0, 2));
        rm1 = fmaxf(rm1, __shfl_xor_sync(0xffffffffu, rm1, 1));
        rm1 = fmaxf(rm1, __shfl_xor_sync(0xffffffffu, rm1, 2));
        float mn0 = fmaxf(mr0, rm0), mn1 = fmaxf(mr1, rm1);
        float cr0 = __expf(mr0 - mn0), cr1 = __expf(mr1 - mn1);
        float s20 = 0.f, s21 = 0.f;
        int r0 = wid*16 + rq;
        #pragma unroll
        for (int j = 0; j < 16; j++) {
            float p0 = __expf(sacc[j][0] - mn0);
            float p1 = __expf(sacc[j][1] - mn0);
            float p2 = __expf(sacc[j][2] - mn1);
            float p3 = __expf(sacc[j][3] - mn1);
            s20 += p0 + p1; s21 += p2 + p3;
            int col = j*8 + c*2;
            Ps[((col  ) << 7) | (r0     ^ xm(col  ))] = f2tf(p0);
            Ps[((col+1) << 7) | (r0     ^ xm(col+1))] = f2tf(p1);
            Ps[((col  ) << 7) | ((r0+8) ^ xm(col  ))] = f2tf(p2);
            Ps[((col+1) << 7) | ((r0+8) ^ xm(col+1))] = f2tf(p3);
        }
        s20 += __shfl_xor_sync(0xffffffffu, s20, 1);
        s20 += __shfl_xor_sync(0xffffffffu, s20, 2);
        s21 += __shfl_xor_sync(0xffffffffu, s21, 1);
        s21 += __shfl_xor_sync(0xffffffffu, s21, 2);
        lr0 = lr0*cr0 + s20;  lr1 = lr1*cr1 + s21;
        mr0 = mn0;            mr1 = mn1;
        #pragma unroll
        for (int j = 0; j < 8; j++) {
            oacc[j][0] *= cr0; oacc[j][1] *= cr0;
            oacc[j][2] *= cr1; oacc[j][3] *= cr1;
        }
        __syncwarp();
        // O += P @ V   (P rows are warp-private)
        #pragma unroll
        for (int ks = 0; ks < 16; ks++) {
            int k0 = ks*8 + c, k1 = k0 + 4;
            int x0 = (c << 3) ^ (((ks*2) & 7) << 2);
            int x1 = (c << 3) ^ (((ks*2+1) & 7) << 2);
            unsigned a[4];
            a[0] = Ps[(k0 << 7) | (r0 ^ x0)];
            a[1] = Ps[(k0 << 7) | ((r0+8) ^ x0)];
            a[2] = Ps[(k1 << 7) | (r0 ^ x1)];
            a[3] = Ps[(k1 << 7) | ((r0+8) ^ x1)];
            #pragma unroll
            for (int j = 0; j < 8; j++) {
                int d = j*8 + rq;
                unsigned b0 = Vs[(k0 << 6) | (d ^ (c << 3))];
                unsigned b1 = Vs[(k1 << 6) | (d ^ (c << 3))];
                mma_tf32(oacc[j], a, b0, b1);
            }
        }
        __syncthreads();
    }

    const int b = bh >> 4, h = bh & 15;
    const int r0 = wid*16 + rq;
    float rl0 = 1.0f / lr0, rl1 = 1.0f / lr1;
    int s0 = qt*128 + r0, s1 = s0 + 8;
    #pragma unroll
    for (int j = 0; j < 8; j++) {
        int d = j*8 + c*2;
        *(float2*)(g_o + ((size_t)(b*S_ + s0))*D_ + h*DK_ + d) =
            make_float2(oacc[j][0]*rl0, oacc[j][1]*rl0);
        *(float2*)(g_o + ((size_t)(b*S_ + s1))*D_ + h*DK_ + d) =
            make_float2(oacc[j][2]*rl1, oacc[j][3]*rl1);
    }
    if (c == 0) {
        g_m[(size_t)bh*S_ + s0] = mr0;  g_l[(size_t)bh*S_ + s0] = lr0;
        g_m[(size_t)bh*S_ + s1] = mr1;  g_l[(size_t)bh*S_ + s1] = lr1;
    }
}

// ====== pass 2: recompute S, write attn = exp(s-m)/l; zeros above diagonal ======
__global__ __launch_bounds__(256) void attn_pass2(float* __restrict__ attn) {
    const int tid = threadIdx.x;
    const int kvt = blockIdx.x, qt = blockIdx.y, bh = blockIdx.z;
    float* base = attn + (size_t)bh * S_ * S_;

    if (kvt > qt) {   // pure zero tile
        float4 z = make_float4(0.f, 0.f, 0.f, 0.f);
        #pragma unroll
        for (int r = 0; r < 16; r++) {
            int id = tid + r*256, row = id >> 5, cg = id & 31;
            *(float4*)(base + (size_t)(qt*128 + row) * S_ + kvt*128 + cg*4) = z;
        }
        return;
    }

    extern __shared__ unsigned smu[];
    unsigned* Qs = smu;
    unsigned* Ks = smu + 8192;
    const int lane = tid & 31, wid = tid >> 5;
    const int c = lane & 3, rq = lane >> 2;
    const float* qb = g_q + (size_t)bh * S_ * DK_;
    const float* kb = g_k + (size_t)bh * S_ * DK_;

    load_kmajor(qb + (size_t)qt*128*DK_, Qs, tid, 0.125f);
    load_kmajor(kb + (size_t)kvt*128*DK_, Ks, tid, 1.0f);
    __syncthreads();

    float sacc[16][4];
    #pragma unroll
    for (int j = 0; j < 16; j++)
        #pragma unroll
        for (int t = 0; t < 4; t++) sacc[j][t] = 0.f;
    s_mma(Qs, Ks, sacc, wid, lane);

    const int r0 = wid*16 + rq, r1 = r0 + 8;
    const int rg0 = qt*128 + r0, rg1 = qt*128 + r1;
    float m0v = g_m[(size_t)bh*S_ + rg0], rl0 = 1.0f / g_l[(size_t)bh*S_ + rg0];
    float m1v = g_m[(size_t)bh*S_ + rg1], rl1 = 1.0f / g_l[(size_t)bh*S_ + rg1];
    const bool diag = (kvt == qt);

    #pragma unroll
    for (int j = 0; j < 16; j++) {
        int colg = kvt*128 + j*8 + c*2;
        float p0 = __expf(sacc[j][0] - m0v) * rl0;
        float p1 = __expf(sacc[j][1] - m0v) * rl0;
        float p2 = __expf(sacc[j][2] - m1v) * rl1;
        float p3 = __expf(sacc[j][3] - m1v) * rl1;
        if (diag) {
            if (colg   > rg0) p0 = 0.f;
            if (colg+1 > rg0) p1 = 0.f;
            if (colg   > rg1) p2 = 0.f;
            if (colg+1 > rg1) p3 = 0.f;
        }
        *(float2*)(base + (size_t)rg0 * S_ + colg) = make_float2(p0, p1);
        *(float2*)(base + (size_t)rg1 * S_ + colg) = make_float2(p2, p3);
    }
}

// ---------------- launcher ----------------
extern "C" void kernel_launch(void* const* d_in, const int* in_sizes, int n_in,
                              void* d_out, int out_size) {
    const float* Q  = (const float*)d_in[0];
    const float* K  = (const float*)d_in[1];
    const float* V  = (const float*)d_in[2];
    const float* Wq = (const float*)d_in[3];
    const float* bq = (const float*)d_in[4];
    const float* Wk = (const float*)d_in[5];
    const float* bk = (const float*)d_in[6];
    const float* Wv = (const float*)d_in[7];
    const float* bv = (const float*)d_in[8];
    const float* Wo = (const float*)d_in[9];
    const float* bo = (const float*)d_in[10];

    float* out = (float*)d_out;
    size_t attn_off = (size_t)M_*D_;
    float* attn = ((size_t)out_size >= attn_off + (size_t)B_*H_*S_*S_)
                  ? out + attn_off : nullptr;

    cudaFuncSetAttribute(qkv_gemm,   cudaFuncAttributeMaxDynamicSharedMemorySize, 65536);
    cudaFuncSetAttribute(out_gemm,   cudaFuncAttributeMaxDynamicSharedMemorySize, 65536);
    cudaFuncSetAttribute(attn_pass1, cudaFuncAttributeMaxDynamicSharedMemorySize, 163840);
    cudaFuncSetAttribute(attn_pass2, cudaFuncAttributeMaxDynamicSharedMemorySize, 65536);

    rope_table_kernel<<<256, 256>>>();
    qkv_gemm<<<dim3(8, 32, 3), 256, 65536>>>(Q, K, V, Wq, Wk, Wv, bq, bk, bv);
    attn_pass1<<<dim3(16, 32), 256, 163840>>>();
    if (attn) attn_pass2<<<dim3(16, 16, 32), 256, 65536>>>(attn);
    out_gemm<<<dim3(8, 32), 256, 65536>>>(Wo, bo, out);
}